// round 1
// baseline (speedup 1.0000x reference)
#include <cuda_runtime.h>
#include <cstdint>

// AdaptiveRankingLoss: pairwise hinge ranking loss over all i<j pairs, N=8192.
//
//   margin  = clamp(0.1*|t_i - t_j|, 0.01, 0.1)
//   hinge   = max(margin - sign(t_i - t_j)*(p_i - p_j), 0)
//   weight  = 1 / (1 + u_i + u_j)
//   loss    = sum_{i<j, t_i != t_j} weight*hinge / count
//
// Compute-bound: 33.5M pairs, ~12 fixed-lat ops + 1 MUFU each. Inputs 96 KB.
// Tiled 256x256 over a 32x32 block grid (upper triangle active), shared-mem
// staging of the j tile, deterministic two-stage reduction.

#define N_ELEMS 8192
#define TILE    256
#define T_GRID  (N_ELEMS / TILE)          // 32
#define NBLK    (T_GRID * T_GRID)         // 1024

__device__ float g_partial_loss[NBLK];
__device__ float g_partial_cnt[NBLK];

__device__ __forceinline__ void pair_term(float ti, float pi, float ui1,
                                          float tj, float pj, float uj,
                                          float& loss, float& cnt) {
    float td = ti - tj;
    float pd = pi - pj;
    // margin = clamp(0.1*|td|, 0.01, 0.1)
    float m = fminf(fmaxf(0.1f * fabsf(td), 0.01f), 0.1f);
    // sp = sign(td) applied to pd (magnitude preserved):  bits(pd) ^ signbit(td)
    float sp = __int_as_float(__float_as_int(pd) ^
                              (__float_as_int(td) & 0x80000000u));
    float h = fmaxf(m - sp, 0.0f);              // hinge
    float w = __fdividef(h, ui1 + uj);          // h / (1 + u_i + u_j), MUFU rcp
    if (td != 0.0f) {                           // tie mask (measure-zero for normals)
        loss += w;
        cnt  += 1.0f;
    }
}

__global__ __launch_bounds__(TILE)
void pair_kernel(const float* __restrict__ p,
                 const float* __restrict__ t,
                 const float* __restrict__ u) {
    const int jt  = blockIdx.x;
    const int it  = blockIdx.y;
    const int bid = it * T_GRID + jt;
    const int tid = threadIdx.x;

    __shared__ float sh_t[TILE];
    __shared__ float sh_p[TILE];
    __shared__ float sh_u[TILE];
    __shared__ float red[16];

    if (jt < it) {  // lower triangle: contribute zeros so stage-2 can sum all blocks
        if (tid == 0) { g_partial_loss[bid] = 0.0f; g_partial_cnt[bid] = 0.0f; }
        return;
    }

    const int jbase = jt * TILE;
    sh_t[tid] = t[jbase + tid];
    sh_p[tid] = p[jbase + tid];
    sh_u[tid] = u[jbase + tid];
    __syncthreads();

    const int i   = it * TILE + tid;
    const float ti  = t[i];
    const float pi  = p[i];
    const float ui1 = 1.0f + u[i];

    float loss = 0.0f, cnt = 0.0f;

    if (it == jt) {
        // diagonal tile: j > i  <=>  jj > tid
        for (int jj = tid + 1; jj < TILE; jj++)
            pair_term(ti, pi, ui1, sh_t[jj], sh_p[jj], sh_u[jj], loss, cnt);
    } else {
        // strictly upper tile: all 256 j's valid
        #pragma unroll 8
        for (int jj = 0; jj < TILE; jj++)
            pair_term(ti, pi, ui1, sh_t[jj], sh_p[jj], sh_u[jj], loss, cnt);
    }

    // block reduction (8 warps)
    #pragma unroll
    for (int o = 16; o; o >>= 1) {
        loss += __shfl_down_sync(0xFFFFFFFFu, loss, o);
        cnt  += __shfl_down_sync(0xFFFFFFFFu, cnt,  o);
    }
    const int lane = tid & 31, wid = tid >> 5;
    if (lane == 0) { red[wid] = loss; red[wid + 8] = cnt; }
    __syncthreads();
    if (wid == 0) {
        float L = (lane < 8) ? red[lane]     : 0.0f;
        float C = (lane < 8) ? red[lane + 8] : 0.0f;
        #pragma unroll
        for (int o = 4; o; o >>= 1) {
            L += __shfl_down_sync(0xFFu, L, o);
            C += __shfl_down_sync(0xFFu, C, o);
        }
        if (lane == 0) { g_partial_loss[bid] = L; g_partial_cnt[bid] = C; }
    }
}

__global__ __launch_bounds__(1024)
void reduce_kernel(float* __restrict__ out) {
    __shared__ float rl[32], rc[32];
    const int tid = threadIdx.x;  // 1024 threads, one per block partial
    float L = g_partial_loss[tid];
    float C = g_partial_cnt[tid];
    #pragma unroll
    for (int o = 16; o; o >>= 1) {
        L += __shfl_down_sync(0xFFFFFFFFu, L, o);
        C += __shfl_down_sync(0xFFFFFFFFu, C, o);
    }
    if ((tid & 31) == 0) { rl[tid >> 5] = L; rc[tid >> 5] = C; }
    __syncthreads();
    if (tid < 32) {
        L = rl[tid];
        C = rc[tid];
        #pragma unroll
        for (int o = 16; o; o >>= 1) {
            L += __shfl_down_sync(0xFFFFFFFFu, L, o);
            C += __shfl_down_sync(0xFFFFFFFFu, C, o);
        }
        if (tid == 0) out[0] = L / fmaxf(C, 1.0f);
    }
}

extern "C" void kernel_launch(void* const* d_in, const int* in_sizes, int n_in,
                              void* d_out, int out_size) {
    const float* predictions   = (const float*)d_in[0];
    const float* targets       = (const float*)d_in[1];
    const float* uncertainties = (const float*)d_in[2];
    float* out = (float*)d_out;

    dim3 grid(T_GRID, T_GRID);
    pair_kernel<<<grid, TILE>>>(predictions, targets, uncertainties);
    reduce_kernel<<<1, 1024>>>(out);
}